// round 15
// baseline (speedup 1.0000x reference)
#include <cuda_runtime.h>
#include <cuda_bf16.h>

#define T_LEN 4096
#define EDIM 1024
#define HDIM 512
#define G3H  1536
#define NTAG 32

__device__ float g_gi[(size_t)T_LEN * 3072];
__device__ float g_hcat[(size_t)T_LEN * EDIM];
__device__ float g_dummy[8];

// ---------------- helpers ----------------
__device__ __forceinline__ unsigned long long ffma2(unsigned long long a,
                                                    unsigned long long b,
                                                    unsigned long long c) {
    unsigned long long d;
    asm("fma.rn.f32x2 %0, %1, %2, %3;" : "=l"(d) : "l"(a), "l"(b), "l"(c));
    return d;
}
__device__ __forceinline__ float sum2(unsigned long long a) {
    float lo, hi;
    asm("mov.b64 {%0, %1}, %2;" : "=f"(lo), "=f"(hi) : "l"(a));
    return lo + hi;
}
__device__ __forceinline__ unsigned long long dup2(float a) {
    unsigned long long d;
    asm("mov.b64 %0, {%1, %1};" : "=l"(d) : "f"(a));
    return d;
}
__device__ __forceinline__ void lds2(unsigned long long& x, unsigned long long& y,
                                     unsigned int a) {
    asm volatile("ld.shared.v2.b64 {%0, %1}, [%2];" : "=l"(x), "=l"(y) : "r"(a));
}
__device__ __forceinline__ float fsig(float x) {
    return __fdividef(1.f, 1.f + __expf(-x));
}
__device__ __forceinline__ float ftanh(float x) {
    return __fdividef(2.f, 1.f + __expf(-2.f * x)) - 1.f;
}
__device__ __forceinline__ unsigned smem_u32(const void* p) {
    return (unsigned)__cvta_generic_to_shared(p);
}
__device__ __forceinline__ void mbar_wait(unsigned addr, unsigned parity) {
    asm volatile(
        "{\n\t.reg .pred P;\n\t"
        "WL_%=:\n\t"
        "mbarrier.try_wait.parity.acquire.cta.shared::cta.b64 P, [%0], %1, 0x989680;\n\t"
        "@P bra.uni WD_%=;\n\t"
        "bra.uni WL_%=;\n\t"
        "WD_%=:\n\t}"
        :: "r"(addr), "r"(parity) : "memory");
}

// ---------------- pad kernels (2 pads => gru_rec_kernel = 6th launch = ncu slot) ----------------
__global__ void pad_kernel(int i) {
    if (threadIdx.x == 0) g_dummy[i] = (float)i;
}

// ---------------- 1) gi GEMM (gather fused): [4096,1024] x [1024,3072] ----------------
// Double buffer with ONE sync per k-tile (store targets the other buffer).
#define GBK 16
#define GPAD 132

__global__ void __launch_bounds__(256, 2)
gemm_gi_kernel(const int* __restrict__ sent, const float* __restrict__ emb,
               const float* __restrict__ Wf, const float* __restrict__ Wb,
               const float* __restrict__ bf_, const float* __restrict__ bb_) {
    __shared__ float As[2][GBK][GPAD];
    __shared__ float Bs[2][GBK][GPAD];

    int tid = threadIdx.x;
    int bx = blockIdx.x, by = blockIdx.y;
    int m0 = by * 128, n0 = bx * 128;

    const float* Bp = (bx < 12) ? (Wf + (size_t)n0 * EDIM)
                                : (Wb + (size_t)(n0 - G3H) * EDIM);
    const float* bp = (bx < 12) ? (bf_ + n0) : (bb_ + (n0 - G3H));

    int lr = tid >> 2;
    int lk = (tid & 3) * 4;

    const float* Ap0 = emb + (size_t)__ldg(sent + m0 + lr) * EDIM;
    const float* Ap1 = emb + (size_t)__ldg(sent + m0 + lr + 64) * EDIM;

    float4 a0r = *(const float4*)(Ap0 + lk);
    float4 a1r = *(const float4*)(Ap1 + lk);
    float4 b0r = *(const float4*)(Bp + (size_t)lr * EDIM + lk);
    float4 b1r = *(const float4*)(Bp + (size_t)(lr + 64) * EDIM + lk);

#define STORE_TILE(B)                                              \
    As[B][lk + 0][lr] = a0r.x; As[B][lk + 1][lr] = a0r.y;          \
    As[B][lk + 2][lr] = a0r.z; As[B][lk + 3][lr] = a0r.w;          \
    As[B][lk + 0][lr + 64] = a1r.x; As[B][lk + 1][lr + 64] = a1r.y;\
    As[B][lk + 2][lr + 64] = a1r.z; As[B][lk + 3][lr + 64] = a1r.w;\
    Bs[B][lk + 0][lr] = b0r.x; Bs[B][lk + 1][lr] = b0r.y;          \
    Bs[B][lk + 2][lr] = b0r.z; Bs[B][lk + 3][lr] = b0r.w;          \
    Bs[B][lk + 0][lr + 64] = b1r.x; Bs[B][lk + 1][lr + 64] = b1r.y;\
    Bs[B][lk + 2][lr + 64] = b1r.z; Bs[B][lk + 3][lr + 64] = b1r.w;

    STORE_TILE(0)
    __syncthreads();

    unsigned long long acc[8][4];
#pragma unroll
    for (int i = 0; i < 8; i++)
#pragma unroll
        for (int j = 0; j < 4; j++) acc[i][j] = 0ull;

    int tx = tid & 15, ty = tid >> 4;
    unsigned int bsBase = smem_u32(&Bs[0][0][0]);
    const unsigned int BUFB = GBK * GPAD * 4;

    for (int kt = 0; kt < EDIM / GBK; kt++) {
        int buf = kt & 1;
        if (kt < EDIM / GBK - 1) {
            int ko = (kt + 1) * GBK + lk;
            a0r = *(const float4*)(Ap0 + ko);
            a1r = *(const float4*)(Ap1 + ko);
            b0r = *(const float4*)(Bp + (size_t)lr * EDIM + ko);
            b1r = *(const float4*)(Bp + (size_t)(lr + 64) * EDIM + ko);
        }
#pragma unroll
        for (int k = 0; k < GBK; k++) {
            float4 av0 = *(const float4*)&As[buf][k][ty * 8];
            float4 av1 = *(const float4*)&As[buf][k][ty * 8 + 4];
            unsigned long long b0, b1, b2, b3;
            unsigned int ba = bsBase + buf * BUFB + (k * GPAD + tx * 8) * 4;
            lds2(b0, b1, ba);
            lds2(b2, b3, ba + 16);
            float av[8] = {av0.x, av0.y, av0.z, av0.w, av1.x, av1.y, av1.z, av1.w};
#pragma unroll
            for (int i = 0; i < 8; i++) {
                unsigned long long ad = dup2(av[i]);
                acc[i][0] = ffma2(ad, b0, acc[i][0]);
                acc[i][1] = ffma2(ad, b1, acc[i][1]);
                acc[i][2] = ffma2(ad, b2, acc[i][2]);
                acc[i][3] = ffma2(ad, b3, acc[i][3]);
            }
        }
        if (kt < EDIM / GBK - 1) {
            int nb = buf ^ 1;
            STORE_TILE(nb)
            __syncthreads();
        }
    }

    float4 bv0 = *(const float4*)(bp + tx * 8);
    float4 bv1 = *(const float4*)(bp + tx * 8 + 4);
    float bias[8] = {bv0.x, bv0.y, bv0.z, bv0.w, bv1.x, bv1.y, bv1.z, bv1.w};
    float* Cp = g_gi + (size_t)(m0 + ty * 8) * 3072 + n0 + tx * 8;
#pragma unroll
    for (int i = 0; i < 8; i++) {
#pragma unroll
        for (int j = 0; j < 4; j++) {
            float lo, hi;
            asm("mov.b64 {%0, %1}, %2;" : "=f"(lo), "=f"(hi) : "l"(acc[i][j]));
            float2 v;
            v.x = lo + bias[2 * j];
            v.y = hi + bias[2 * j + 1];
            *(float2*)(Cp + (size_t)i * 3072 + 2 * j) = v;
        }
    }
}

// ---------------- 2) recurrence (best-known structure, unchanged) ----------------
#define RTHR 384

__global__ void __launch_bounds__(RTHR, 1)
gru_rec_kernel(const float* __restrict__ Whh_f, const float* __restrict__ Whh_b,
               const float* __restrict__ bhh_f, const float* __restrict__ bhh_b) {
    __shared__ __align__(16) float hbuf[2][HDIM];
    __shared__ __align__(16) float partials[96 * 4];
    __shared__ __align__(8) unsigned long long mbar2[2];

    const int tid = threadIdx.x;
    const int rank = blockIdx.x & 15;
    const int dir = blockIdx.x >> 4;

    const float* Whh = dir ? Whh_b : Whh_f;
    const float* bhh = dir ? bhh_b : bhh_f;

    const int row = tid % 96;
    const int chunk = tid / 96;
    const int seg = row >> 5;
    const int jj = row & 31;
    const int grow = seg * HDIM + rank * 32 + jj;

    unsigned long long w[64];
    {
        const unsigned long long* wp =
            (const unsigned long long*)(Whh + (size_t)grow * HDIM + chunk * 128);
#pragma unroll
        for (int q = 0; q < 64; q++) w[q] = wp[q];
    }

    const int lane = tid & 31;
    const int gwarp = tid >> 5;            // 0..2 for gate warps
    const int hidx = rank * 32 + lane;
    float bhr = 0.f, bhz = 0.f, bhn = 0.f;
    if (tid < 96) {
        bhr = bhh[hidx];
        bhz = bhh[HDIM + hidx];
        bhn = bhh[2 * HDIM + hidx];
    }
    const int prBeg = (gwarp == 0) ? 0 : (gwarp == 1 ? 6 : 11);
    const int prEnd = (gwarp == 0) ? 6 : (gwarp == 1 ? 11 : 16);

    const unsigned hbase = smem_u32(&hbuf[0][0]);
    const unsigned mbase = smem_u32(&mbar2[0]);
    const unsigned pbase = smem_u32(&partials[0]);

    if (tid == 0) {
        asm volatile("mbarrier.init.shared.b64 [%0], %1;" :: "r"(mbase), "r"(1) : "memory");
        asm volatile("mbarrier.init.shared.b64 [%0], %1;" :: "r"(mbase + 8), "r"(1) : "memory");
    }
    for (int i = tid; i < HDIM; i += RTHR) hbuf[0][i] = 0.f;
    __syncthreads();
    asm volatile("barrier.cluster.arrive.aligned;" ::: "memory");
    asm volatile("barrier.cluster.wait.aligned;" ::: "memory");

    const float* gi_dir = g_gi + dir * G3H;
    const unsigned hbb = hbase + chunk * 512;

    // prefetch gi for t=0
    float gir = 0.f, giz = 0.f, gin = 0.f;
    if (tid < 96) {
        const int p0 = dir ? (T_LEN - 1) : 0;
        const float* g = gi_dir + (size_t)p0 * 3072;
        gir = g[hidx];
        giz = g[HDIM + hidx];
        gin = g[2 * HDIM + hidx];
    }

    for (int t = 0; t < T_LEN; t++) {
        const int p = dir ? (T_LEN - 1 - t) : t;
        const int cur = t & 1;
        const int nxt = cur ^ 1;
        const unsigned mb_cur = mbase + cur * 8;

        if (tid == 0) {
            asm volatile("mbarrier.arrive.expect_tx.shared.b64 _, [%0], %1;"
                         :: "r"(mb_cur), "r"(HDIM * 4) : "memory");
        }

        float hold = 0.f;
        if (tid < 96) hold = hbuf[cur][hidx];

        // GEMV: 128 MACs/thread as 64 FFMA2 (h broadcast LDS), 4 accumulators
        unsigned long long a0 = 0ull, a1 = 0ull, a2 = 0ull, a3 = 0ull;
        const unsigned hb = hbb + cur * (HDIM * 4);
#pragma unroll
        for (int q = 0; q < 16; q++) {
            unsigned long long h0, h1, h2, h3;
            lds2(h0, h1, hb + q * 32);
            lds2(h2, h3, hb + q * 32 + 16);
            a0 = ffma2(w[4 * q + 0], h0, a0);
            a1 = ffma2(w[4 * q + 1], h1, a1);
            a2 = ffma2(w[4 * q + 2], h2, a2);
            a3 = ffma2(w[4 * q + 3], h3, a3);
        }
        partials[row * 4 + chunk] = (sum2(a0) + sum2(a1)) + (sum2(a2) + sum2(a3));

        if (tid >= 96) {
            asm volatile("bar.arrive 1, %0;" :: "n"(RTHR) : "memory");
        } else {
            asm volatile("bar.sync 1, %0;" :: "n"(RTHR) : "memory");

            // one-stage reduce: 3x LDS.128 + horizontal sums
            float4 p4;
            unsigned pa = pbase + lane * 16;
            asm volatile("ld.shared.v4.f32 {%0,%1,%2,%3}, [%4];"
                         : "=f"(p4.x), "=f"(p4.y), "=f"(p4.z), "=f"(p4.w)
                         : "r"(pa));
            float hr = (p4.x + p4.y) + (p4.z + p4.w);
            asm volatile("ld.shared.v4.f32 {%0,%1,%2,%3}, [%4];"
                         : "=f"(p4.x), "=f"(p4.y), "=f"(p4.z), "=f"(p4.w)
                         : "r"(pa + 32 * 16));
            float hz = (p4.x + p4.y) + (p4.z + p4.w);
            asm volatile("ld.shared.v4.f32 {%0,%1,%2,%3}, [%4];"
                         : "=f"(p4.x), "=f"(p4.y), "=f"(p4.z), "=f"(p4.w)
                         : "r"(pa + 64 * 16));
            float hn = (p4.x + p4.y) + (p4.z + p4.w);

            float r = fsig(gir + hr + bhr);
            float z = fsig(giz + hz + bhz);
            float n = ftanh(gin + r * (hn + bhn));
            float hnew = (1.f - z) * n + z * hold;

            unsigned lh = hbase + (unsigned)(nxt * HDIM + hidx) * 4;
            unsigned hv = __float_as_uint(hnew);
            for (int pr = prBeg; pr < prEnd; pr++) {
                unsigned rh, rm;
                asm volatile("mapa.shared::cluster.u32 %0, %1, %2;"
                             : "=r"(rh) : "r"(lh), "r"(pr));
                asm volatile("mapa.shared::cluster.u32 %0, %1, %2;"
                             : "=r"(rm) : "r"(mb_cur), "r"(pr));
                asm volatile(
                    "st.async.shared::cluster.mbarrier::complete_tx::bytes.b32 [%0], %1, [%2];"
                    :: "r"(rh), "r"(hv), "r"(rm) : "memory");
            }
            if (gwarp == 0)
                g_hcat[(size_t)p * EDIM + dir * HDIM + hidx] = hnew;

            // prefetch gi for t+1
            if (t + 1 < T_LEN) {
                const int p2 = dir ? (T_LEN - 2 - t) : (t + 1);
                const float* g2 = gi_dir + (size_t)p2 * 3072;
                gir = g2[hidx];
                giz = g2[HDIM + hidx];
                gin = g2[2 * HDIM + hidx];
            }
        }

        mbar_wait(mb_cur, (t >> 1) & 1);
    }

    asm volatile("barrier.cluster.arrive.aligned;" ::: "memory");
    asm volatile("barrier.cluster.wait.aligned;" ::: "memory");
}

// ---------------- 3) output GEMM (Wout smem-cached) ----------------
__global__ void __launch_bounds__(256)
out_kernel(const float* __restrict__ Wout, float* __restrict__ out) {
    extern __shared__ float4 Ws4[];   // [256][32]
    int tid = threadIdx.x;

    for (int i = 0; i < 32; i++) {
        int idx = tid + i * 256;
        int n = idx >> 8;
        int k4 = idx & 255;
        Ws4[k4 * 32 + n] = *(const float4*)(Wout + (size_t)n * EDIM + k4 * 4);
    }
    __syncthreads();

    int n = tid & 31;
    int wrp = tid >> 5;
    int t0 = blockIdx.x * 32 + wrp * 4;

    const float4* h0 = (const float4*)(g_hcat + (size_t)(t0 + 0) * EDIM);
    const float4* h1 = (const float4*)(g_hcat + (size_t)(t0 + 1) * EDIM);
    const float4* h2 = (const float4*)(g_hcat + (size_t)(t0 + 2) * EDIM);
    const float4* h3 = (const float4*)(g_hcat + (size_t)(t0 + 3) * EDIM);

    float acc0 = 0.f, acc1 = 0.f, acc2 = 0.f, acc3 = 0.f;
#pragma unroll 4
    for (int k4 = 0; k4 < 256; k4++) {
        float4 wv = Ws4[k4 * 32 + n];
        float4 a = h0[k4], b = h1[k4], c = h2[k4], d = h3[k4];
        acc0 += wv.x * a.x + wv.y * a.y + wv.z * a.z + wv.w * a.w;
        acc1 += wv.x * b.x + wv.y * b.y + wv.z * b.z + wv.w * b.w;
        acc2 += wv.x * c.x + wv.y * c.y + wv.z * c.z + wv.w * c.w;
        acc3 += wv.x * d.x + wv.y * d.y + wv.z * d.z + wv.w * d.w;
    }
    out[(size_t)(t0 + 0) * NTAG + n] = acc0;
    out[(size_t)(t0 + 1) * NTAG + n] = acc1;
    out[(size_t)(t0 + 2) * NTAG + n] = acc2;
    out[(size_t)(t0 + 3) * NTAG + n] = acc3;
}

// ---------------- launch ----------------
extern "C" void kernel_launch(void* const* d_in, const int* in_sizes, int n_in,
                              void* d_out, int out_size) {
    const int* sentence   = (const int*)d_in[0];
    const float* emb      = (const float*)d_in[1];
    const float* W_ih_f   = (const float*)d_in[2];
    const float* W_hh_f   = (const float*)d_in[3];
    const float* b_ih_f   = (const float*)d_in[4];
    const float* b_hh_f   = (const float*)d_in[5];
    const float* W_ih_b   = (const float*)d_in[6];
    const float* W_hh_b   = (const float*)d_in[7];
    const float* b_ih_b   = (const float*)d_in[8];
    const float* b_hh_b   = (const float*)d_in[9];
    const float* W_out    = (const float*)d_in[10];
    float* out = (float*)d_out;

    static int init_done = 0;
    if (!init_done) {
        cudaFuncSetAttribute(gru_rec_kernel,
                             cudaFuncAttributeNonPortableClusterSizeAllowed, 1);
        cudaFuncSetAttribute(out_kernel,
                             cudaFuncAttributeMaxDynamicSharedMemorySize, 131072);
        init_done = 1;
    }

    dim3 ggrid(24, 32);
    gemm_gi_kernel<<<ggrid, 256>>>(sentence, emb, W_ih_f, W_ih_b, b_ih_f, b_ih_b);

    // 2 pads keep gru_rec_kernel in the ncu capture slot (#6 overall,
    // verified in R11/R12)
    pad_kernel<<<1, 32>>>(0);
    pad_kernel<<<1, 32>>>(1);

    cudaLaunchConfig_t cfg = {};
    cfg.gridDim = dim3(32, 1, 1);
    cfg.blockDim = dim3(RTHR, 1, 1);
    cfg.dynamicSmemBytes = 0;
    cfg.stream = 0;
    cudaLaunchAttribute attrs[1];
    attrs[0].id = cudaLaunchAttributeClusterDimension;
    attrs[0].val.clusterDim.x = 16;
    attrs[0].val.clusterDim.y = 1;
    attrs[0].val.clusterDim.z = 1;
    cfg.attrs = attrs;
    cfg.numAttrs = 1;
    cudaLaunchKernelEx(&cfg, gru_rec_kernel, W_hh_f, W_hh_b, b_hh_f, b_hh_b);

    out_kernel<<<T_LEN / 32, 256, 131072>>>(W_out, out);
}

// round 16
// speedup vs baseline: 1.0411x; 1.0411x over previous
#include <cuda_runtime.h>
#include <cuda_bf16.h>

#define T_LEN 4096
#define EDIM 1024
#define HDIM 512
#define G3H  1536
#define NTAG 32

__device__ float g_gi[(size_t)T_LEN * 3072];
__device__ float g_hcat[(size_t)T_LEN * EDIM];

// ---------------- helpers ----------------
__device__ __forceinline__ unsigned long long ffma2(unsigned long long a,
                                                    unsigned long long b,
                                                    unsigned long long c) {
    unsigned long long d;
    asm("fma.rn.f32x2 %0, %1, %2, %3;" : "=l"(d) : "l"(a), "l"(b), "l"(c));
    return d;
}
__device__ __forceinline__ float sum2(unsigned long long a) {
    float lo, hi;
    asm("mov.b64 {%0, %1}, %2;" : "=f"(lo), "=f"(hi) : "l"(a));
    return lo + hi;
}
__device__ __forceinline__ unsigned long long dup2(float a) {
    unsigned long long d;
    asm("mov.b64 %0, {%1, %1};" : "=l"(d) : "f"(a));
    return d;
}
__device__ __forceinline__ void lds2(unsigned long long& x, unsigned long long& y,
                                     unsigned int a) {
    asm volatile("ld.shared.v2.b64 {%0, %1}, [%2];" : "=l"(x), "=l"(y) : "r"(a));
}
__device__ __forceinline__ float fsig(float x) {
    return __fdividef(1.f, 1.f + __expf(-x));
}
__device__ __forceinline__ float ftanh(float x) {
    return __fdividef(2.f, 1.f + __expf(-2.f * x)) - 1.f;
}
__device__ __forceinline__ unsigned smem_u32(const void* p) {
    return (unsigned)__cvta_generic_to_shared(p);
}
__device__ __forceinline__ void mbar_wait(unsigned addr, unsigned parity) {
    asm volatile(
        "{\n\t.reg .pred P;\n\t"
        "WL_%=:\n\t"
        "mbarrier.try_wait.parity.acquire.cta.shared::cta.b64 P, [%0], %1, 0x989680;\n\t"
        "@P bra.uni WD_%=;\n\t"
        "bra.uni WL_%=;\n\t"
        "WD_%=:\n\t}"
        :: "r"(addr), "r"(parity) : "memory");
}

// ---------------- 1) gi GEMM (gather fused): [4096,1024] x [1024,3072] ----------------
// Double buffer with ONE sync per k-tile (store targets the other buffer).
#define GBK 16
#define GPAD 132

__global__ void __launch_bounds__(256, 2)
gemm_gi_kernel(const int* __restrict__ sent, const float* __restrict__ emb,
               const float* __restrict__ Wf, const float* __restrict__ Wb,
               const float* __restrict__ bf_, const float* __restrict__ bb_) {
    __shared__ float As[2][GBK][GPAD];
    __shared__ float Bs[2][GBK][GPAD];

    int tid = threadIdx.x;
    int bx = blockIdx.x, by = blockIdx.y;
    int m0 = by * 128, n0 = bx * 128;

    const float* Bp = (bx < 12) ? (Wf + (size_t)n0 * EDIM)
                                : (Wb + (size_t)(n0 - G3H) * EDIM);
    const float* bp = (bx < 12) ? (bf_ + n0) : (bb_ + (n0 - G3H));

    int lr = tid >> 2;
    int lk = (tid & 3) * 4;

    const float* Ap0 = emb + (size_t)__ldg(sent + m0 + lr) * EDIM;
    const float* Ap1 = emb + (size_t)__ldg(sent + m0 + lr + 64) * EDIM;

    float4 a0r = *(const float4*)(Ap0 + lk);
    float4 a1r = *(const float4*)(Ap1 + lk);
    float4 b0r = *(const float4*)(Bp + (size_t)lr * EDIM + lk);
    float4 b1r = *(const float4*)(Bp + (size_t)(lr + 64) * EDIM + lk);

#define STORE_TILE(B)                                              \
    As[B][lk + 0][lr] = a0r.x; As[B][lk + 1][lr] = a0r.y;          \
    As[B][lk + 2][lr] = a0r.z; As[B][lk + 3][lr] = a0r.w;          \
    As[B][lk + 0][lr + 64] = a1r.x; As[B][lk + 1][lr + 64] = a1r.y;\
    As[B][lk + 2][lr + 64] = a1r.z; As[B][lk + 3][lr + 64] = a1r.w;\
    Bs[B][lk + 0][lr] = b0r.x; Bs[B][lk + 1][lr] = b0r.y;          \
    Bs[B][lk + 2][lr] = b0r.z; Bs[B][lk + 3][lr] = b0r.w;          \
    Bs[B][lk + 0][lr + 64] = b1r.x; Bs[B][lk + 1][lr + 64] = b1r.y;\
    Bs[B][lk + 2][lr + 64] = b1r.z; Bs[B][lk + 3][lr + 64] = b1r.w;

    STORE_TILE(0)
    __syncthreads();

    unsigned long long acc[8][4];
#pragma unroll
    for (int i = 0; i < 8; i++)
#pragma unroll
        for (int j = 0; j < 4; j++) acc[i][j] = 0ull;

    int tx = tid & 15, ty = tid >> 4;
    unsigned int bsBase = smem_u32(&Bs[0][0][0]);
    const unsigned int BUFB = GBK * GPAD * 4;

    for (int kt = 0; kt < EDIM / GBK; kt++) {
        int buf = kt & 1;
        if (kt < EDIM / GBK - 1) {
            int ko = (kt + 1) * GBK + lk;
            a0r = *(const float4*)(Ap0 + ko);
            a1r = *(const float4*)(Ap1 + ko);
            b0r = *(const float4*)(Bp + (size_t)lr * EDIM + ko);
            b1r = *(const float4*)(Bp + (size_t)(lr + 64) * EDIM + ko);
        }
#pragma unroll
        for (int k = 0; k < GBK; k++) {
            float4 av0 = *(const float4*)&As[buf][k][ty * 8];
            float4 av1 = *(const float4*)&As[buf][k][ty * 8 + 4];
            unsigned long long b0, b1, b2, b3;
            unsigned int ba = bsBase + buf * BUFB + (k * GPAD + tx * 8) * 4;
            lds2(b0, b1, ba);
            lds2(b2, b3, ba + 16);
            float av[8] = {av0.x, av0.y, av0.z, av0.w, av1.x, av1.y, av1.z, av1.w};
#pragma unroll
            for (int i = 0; i < 8; i++) {
                unsigned long long ad = dup2(av[i]);
                acc[i][0] = ffma2(ad, b0, acc[i][0]);
                acc[i][1] = ffma2(ad, b1, acc[i][1]);
                acc[i][2] = ffma2(ad, b2, acc[i][2]);
                acc[i][3] = ffma2(ad, b3, acc[i][3]);
            }
        }
        if (kt < EDIM / GBK - 1) {
            int nb = buf ^ 1;
            STORE_TILE(nb)
            __syncthreads();
        }
    }

    float4 bv0 = *(const float4*)(bp + tx * 8);
    float4 bv1 = *(const float4*)(bp + tx * 8 + 4);
    float bias[8] = {bv0.x, bv0.y, bv0.z, bv0.w, bv1.x, bv1.y, bv1.z, bv1.w};
    float* Cp = g_gi + (size_t)(m0 + ty * 8) * 3072 + n0 + tx * 8;
#pragma unroll
    for (int i = 0; i < 8; i++) {
#pragma unroll
        for (int j = 0; j < 4; j++) {
            float lo, hi;
            asm("mov.b64 {%0, %1}, %2;" : "=f"(lo), "=f"(hi) : "l"(acc[i][j]));
            float2 v;
            v.x = lo + bias[2 * j];
            v.y = hi + bias[2 * j + 1];
            *(float2*)(Cp + (size_t)i * 3072 + 2 * j) = v;
        }
    }
}

// ---------------- 2) recurrence (best-known + expect_tx moved off gate warp) ----------------
#define RTHR 384

__global__ void __launch_bounds__(RTHR, 1)
gru_rec_kernel(const float* __restrict__ Whh_f, const float* __restrict__ Whh_b,
               const float* __restrict__ bhh_f, const float* __restrict__ bhh_b) {
    __shared__ __align__(16) float hbuf[2][HDIM];
    __shared__ __align__(16) float partials[96 * 4];
    __shared__ __align__(8) unsigned long long mbar2[2];

    const int tid = threadIdx.x;
    const int rank = blockIdx.x & 15;
    const int dir = blockIdx.x >> 4;

    const float* Whh = dir ? Whh_b : Whh_f;
    const float* bhh = dir ? bhh_b : bhh_f;

    const int row = tid % 96;
    const int chunk = tid / 96;
    const int seg = row >> 5;
    const int jj = row & 31;
    const int grow = seg * HDIM + rank * 32 + jj;

    unsigned long long w[64];
    {
        const unsigned long long* wp =
            (const unsigned long long*)(Whh + (size_t)grow * HDIM + chunk * 128);
#pragma unroll
        for (int q = 0; q < 64; q++) w[q] = wp[q];
    }

    const int lane = tid & 31;
    const int gwarp = tid >> 5;            // 0..2 for gate warps
    const int hidx = rank * 32 + lane;
    float bhr = 0.f, bhz = 0.f, bhn = 0.f;
    if (tid < 96) {
        bhr = bhh[hidx];
        bhz = bhh[HDIM + hidx];
        bhn = bhh[2 * HDIM + hidx];
    }
    const int prBeg = (gwarp == 0) ? 0 : (gwarp == 1 ? 6 : 11);
    const int prEnd = (gwarp == 0) ? 6 : (gwarp == 1 ? 11 : 16);

    const unsigned hbase = smem_u32(&hbuf[0][0]);
    const unsigned mbase = smem_u32(&mbar2[0]);
    const unsigned pbase = smem_u32(&partials[0]);

    if (tid == 0) {
        asm volatile("mbarrier.init.shared.b64 [%0], %1;" :: "r"(mbase), "r"(1) : "memory");
        asm volatile("mbarrier.init.shared.b64 [%0], %1;" :: "r"(mbase + 8), "r"(1) : "memory");
    }
    for (int i = tid; i < HDIM; i += RTHR) hbuf[0][i] = 0.f;
    __syncthreads();
    asm volatile("barrier.cluster.arrive.aligned;" ::: "memory");
    asm volatile("barrier.cluster.wait.aligned;" ::: "memory");

    const float* gi_dir = g_gi + dir * G3H;
    const unsigned hbb = hbase + chunk * 512;

    // prefetch gi for t=0
    float gir = 0.f, giz = 0.f, gin = 0.f;
    if (tid < 96) {
        const int p0 = dir ? (T_LEN - 1) : 0;
        const float* g = gi_dir + (size_t)p0 * 3072;
        gir = g[hidx];
        giz = g[HDIM + hidx];
        gin = g[2 * HDIM + hidx];
    }

    for (int t = 0; t < T_LEN; t++) {
        const int p = dir ? (T_LEN - 1 - t) : t;
        const int cur = t & 1;
        const int nxt = cur ^ 1;
        const unsigned mb_cur = mbase + cur * 8;

        // expect_tx posted by a WORKER lane (slack timeline), not gate warp 0:
        // tx arriving before the expect is pending-counted by the mbarrier, and
        // this thread posts it before its own wait each step.
        if (tid == RTHR - 1) {
            asm volatile("mbarrier.arrive.expect_tx.shared.b64 _, [%0], %1;"
                         :: "r"(mb_cur), "r"(HDIM * 4) : "memory");
        }

        float hold = 0.f;
        if (tid < 96) hold = hbuf[cur][hidx];

        // GEMV: 128 MACs/thread as 64 FFMA2 (h broadcast LDS), 4 accumulators
        unsigned long long a0 = 0ull, a1 = 0ull, a2 = 0ull, a3 = 0ull;
        const unsigned hb = hbb + cur * (HDIM * 4);
#pragma unroll
        for (int q = 0; q < 16; q++) {
            unsigned long long h0, h1, h2, h3;
            lds2(h0, h1, hb + q * 32);
            lds2(h2, h3, hb + q * 32 + 16);
            a0 = ffma2(w[4 * q + 0], h0, a0);
            a1 = ffma2(w[4 * q + 1], h1, a1);
            a2 = ffma2(w[4 * q + 2], h2, a2);
            a3 = ffma2(w[4 * q + 3], h3, a3);
        }
        partials[row * 4 + chunk] = (sum2(a0) + sum2(a1)) + (sum2(a2) + sum2(a3));

        if (tid >= 96) {
            asm volatile("bar.arrive 1, %0;" :: "n"(RTHR) : "memory");
        } else {
            asm volatile("bar.sync 1, %0;" :: "n"(RTHR) : "memory");

            // one-stage reduce: 3x LDS.128 + horizontal sums
            float4 p4;
            unsigned pa = pbase + lane * 16;
            asm volatile("ld.shared.v4.f32 {%0,%1,%2,%3}, [%4];"
                         : "=f"(p4.x), "=f"(p4.y), "=f"(p4.z), "=f"(p4.w)
                         : "r"(pa));
            float hr = (p4.x + p4.y) + (p4.z + p4.w);
            asm volatile("ld.shared.v4.f32 {%0,%1,%2,%3}, [%4];"
                         : "=f"(p4.x), "=f"(p4.y), "=f"(p4.z), "=f"(p4.w)
                         : "r"(pa + 32 * 16));
            float hz = (p4.x + p4.y) + (p4.z + p4.w);
            asm volatile("ld.shared.v4.f32 {%0,%1,%2,%3}, [%4];"
                         : "=f"(p4.x), "=f"(p4.y), "=f"(p4.z), "=f"(p4.w)
                         : "r"(pa + 64 * 16));
            float hn = (p4.x + p4.y) + (p4.z + p4.w);

            float r = fsig(gir + hr + bhr);
            float z = fsig(giz + hz + bhz);
            float n = ftanh(gin + r * (hn + bhn));
            float hnew = (1.f - z) * n + z * hold;

            unsigned lh = hbase + (unsigned)(nxt * HDIM + hidx) * 4;
            unsigned hv = __float_as_uint(hnew);
            for (int pr = prBeg; pr < prEnd; pr++) {
                unsigned rh, rm;
                asm volatile("mapa.shared::cluster.u32 %0, %1, %2;"
                             : "=r"(rh) : "r"(lh), "r"(pr));
                asm volatile("mapa.shared::cluster.u32 %0, %1, %2;"
                             : "=r"(rm) : "r"(mb_cur), "r"(pr));
                asm volatile(
                    "st.async.shared::cluster.mbarrier::complete_tx::bytes.b32 [%0], %1, [%2];"
                    :: "r"(rh), "r"(hv), "r"(rm) : "memory");
            }
            if (gwarp == 0)
                g_hcat[(size_t)p * EDIM + dir * HDIM + hidx] = hnew;

            // prefetch gi for t+1
            if (t + 1 < T_LEN) {
                const int p2 = dir ? (T_LEN - 2 - t) : (t + 1);
                const float* g2 = gi_dir + (size_t)p2 * 3072;
                gir = g2[hidx];
                giz = g2[HDIM + hidx];
                gin = g2[2 * HDIM + hidx];
            }
        }

        mbar_wait(mb_cur, (t >> 1) & 1);
    }

    asm volatile("barrier.cluster.arrive.aligned;" ::: "memory");
    asm volatile("barrier.cluster.wait.aligned;" ::: "memory");
}

// ---------------- 3) output GEMM (Wout smem-cached) ----------------
__global__ void __launch_bounds__(256)
out_kernel(const float* __restrict__ Wout, float* __restrict__ out) {
    extern __shared__ float4 Ws4[];   // [256][32]
    int tid = threadIdx.x;

    for (int i = 0; i < 32; i++) {
        int idx = tid + i * 256;
        int n = idx >> 8;
        int k4 = idx & 255;
        Ws4[k4 * 32 + n] = *(const float4*)(Wout + (size_t)n * EDIM + k4 * 4);
    }
    __syncthreads();

    int n = tid & 31;
    int wrp = tid >> 5;
    int t0 = blockIdx.x * 32 + wrp * 4;

    const float4* h0 = (const float4*)(g_hcat + (size_t)(t0 + 0) * EDIM);
    const float4* h1 = (const float4*)(g_hcat + (size_t)(t0 + 1) * EDIM);
    const float4* h2 = (const float4*)(g_hcat + (size_t)(t0 + 2) * EDIM);
    const float4* h3 = (const float4*)(g_hcat + (size_t)(t0 + 3) * EDIM);

    float acc0 = 0.f, acc1 = 0.f, acc2 = 0.f, acc3 = 0.f;
#pragma unroll 4
    for (int k4 = 0; k4 < 256; k4++) {
        float4 wv = Ws4[k4 * 32 + n];
        float4 a = h0[k4], b = h1[k4], c = h2[k4], d = h3[k4];
        acc0 += wv.x * a.x + wv.y * a.y + wv.z * a.z + wv.w * a.w;
        acc1 += wv.x * b.x + wv.y * b.y + wv.z * b.z + wv.w * b.w;
        acc2 += wv.x * c.x + wv.y * c.y + wv.z * c.z + wv.w * c.w;
        acc3 += wv.x * d.x + wv.y * d.y + wv.z * d.z + wv.w * d.w;
    }
    out[(size_t)(t0 + 0) * NTAG + n] = acc0;
    out[(size_t)(t0 + 1) * NTAG + n] = acc1;
    out[(size_t)(t0 + 2) * NTAG + n] = acc2;
    out[(size_t)(t0 + 3) * NTAG + n] = acc3;
}

// ---------------- launch ----------------
extern "C" void kernel_launch(void* const* d_in, const int* in_sizes, int n_in,
                              void* d_out, int out_size) {
    const int* sentence   = (const int*)d_in[0];
    const float* emb      = (const float*)d_in[1];
    const float* W_ih_f   = (const float*)d_in[2];
    const float* W_hh_f   = (const float*)d_in[3];
    const float* b_ih_f   = (const float*)d_in[4];
    const float* b_hh_f   = (const float*)d_in[5];
    const float* W_ih_b   = (const float*)d_in[6];
    const float* W_hh_b   = (const float*)d_in[7];
    const float* b_ih_b   = (const float*)d_in[8];
    const float* b_hh_b   = (const float*)d_in[9];
    const float* W_out    = (const float*)d_in[10];
    float* out = (float*)d_out;

    static int init_done = 0;
    if (!init_done) {
        cudaFuncSetAttribute(gru_rec_kernel,
                             cudaFuncAttributeNonPortableClusterSizeAllowed, 1);
        cudaFuncSetAttribute(out_kernel,
                             cudaFuncAttributeMaxDynamicSharedMemorySize, 131072);
        init_done = 1;
    }

    dim3 ggrid(24, 32);
    gemm_gi_kernel<<<ggrid, 256>>>(sentence, emb, W_ih_f, W_ih_b, b_ih_f, b_ih_b);

    cudaLaunchConfig_t cfg = {};
    cfg.gridDim = dim3(32, 1, 1);
    cfg.blockDim = dim3(RTHR, 1, 1);
    cfg.dynamicSmemBytes = 0;
    cfg.stream = 0;
    cudaLaunchAttribute attrs[1];
    attrs[0].id = cudaLaunchAttributeClusterDimension;
    attrs[0].val.clusterDim.x = 16;
    attrs[0].val.clusterDim.y = 1;
    attrs[0].val.clusterDim.z = 1;
    cfg.attrs = attrs;
    cfg.numAttrs = 1;
    cudaLaunchKernelEx(&cfg, gru_rec_kernel, W_hh_f, W_hh_b, b_hh_f, b_hh_b);

    out_kernel<<<T_LEN / 32, 256, 131072>>>(W_out, out);
}